// round 1
// baseline (speedup 1.0000x reference)
#include <cuda_runtime.h>

// Problem constants (fixed by setup_inputs)
#define BB 4
#define CC 128
#define HH 96
#define WW 160
#define RR 4
#define SS 17   // 1 + 4*R

// Tiling
#define TW 32          // tile width in pixels
#define TH 8           // tile height in pixels
#define PX 2           // pixels per thread along w
#define BX (TW / PX)   // 16
#define BY TH          // 8
#define NTHREADS (BX * BY)  // 128
#define HALO_W (TW + 2 * RR)  // 40
#define HALO_H (TH + 2 * RR)  // 16

__global__ __launch_bounds__(NTHREADS)
void cost_volume_kernel(const float* __restrict__ src,
                        const float* __restrict__ tgt,
                        float* __restrict__ out) {
    // two channels staged per iteration
    __shared__ float sm[2][HALO_H][HALO_W];

    const int tx = threadIdx.x;
    const int ty = threadIdx.y;
    const int tid = ty * BX + tx;
    const int w0 = blockIdx.x * TW;
    const int h0 = blockIdx.y * TH;
    const int b  = blockIdx.z;
    const int lx = 2 * tx;          // local col of pixel 0
    const int w  = w0 + lx;
    const int h  = h0 + ty;

    float a0[SS], a1[SS];
#pragma unroll
    for (int s = 0; s < SS; s++) { a0[s] = 0.f; a1[s] = 0.f; }

    const float* srcp = src + (((long long)b * CC) * HH + h) * WW + w;
    const float* tgtb = tgt + (long long)b * CC * HH * WW;

    for (int c0 = 0; c0 < CC; c0 += 2) {
        __syncthreads();   // protect smem from previous iteration's readers
        // cooperative load of two channel halo tiles (zero-padded at borders)
#pragma unroll
        for (int i = tid; i < 2 * HALO_H * HALO_W; i += NTHREADS) {
            int ch  = i / (HALO_H * HALO_W);
            int rem = i - ch * (HALO_H * HALO_W);
            int r   = rem / HALO_W;
            int cl  = rem - r * HALO_W;
            int gr  = h0 - RR + r;
            int gc  = w0 - RR + cl;
            float v = 0.f;
            if ((unsigned)gr < (unsigned)HH && (unsigned)gc < (unsigned)WW)
                v = tgtb[((c0 + ch) * HH + gr) * WW + gc];
            sm[ch][r][cl] = v;
        }
        __syncthreads();

#pragma unroll
        for (int ch = 0; ch < 2; ch++) {
            const float2 sv = *(const float2*)(srcp + (long long)(c0 + ch) * HH * WW);

            // horizontal row (dh = 0): cols lx .. lx+9  -> vals[0..9]
            float vals[10];
#pragma unroll
            for (int j = 0; j < 5; j++) {
                float2 t = *(const float2*)&sm[ch][ty + RR][lx + 2 * j];
                vals[2 * j]     = t.x;
                vals[2 * j + 1] = t.y;
            }
            // s = 0 : (0,0)
            a0[0] += sv.x * vals[4];
            a1[0] += sv.y * vals[5];
            // s = 4i-1 : (0,-i) ; s = 4i : (0,+i)
#pragma unroll
            for (int i2 = 1; i2 <= RR; i2++) {
                a0[4 * i2 - 1] += sv.x * vals[4 - i2];
                a0[4 * i2]     += sv.x * vals[4 + i2];
                a1[4 * i2 - 1] += sv.y * vals[5 - i2];
                a1[4 * i2]     += sv.y * vals[5 + i2];
            }
            // vertical: s = 4i-3 : (-i,0) ; s = 4i-2 : (+i,0)
#pragma unroll
            for (int i2 = 1; i2 <= RR; i2++) {
                float2 tu = *(const float2*)&sm[ch][ty + RR - i2][lx + RR];
                float2 td = *(const float2*)&sm[ch][ty + RR + i2][lx + RR];
                a0[4 * i2 - 3] += sv.x * tu.x;
                a1[4 * i2 - 3] += sv.y * tu.y;
                a0[4 * i2 - 2] += sv.x * td.x;
                a1[4 * i2 - 2] += sv.y * td.y;
            }
        }
    }

    // write out: out[b][s][h][w], two consecutive w per thread
#pragma unroll
    for (int s = 0; s < SS; s++) {
        float2 o = make_float2(a0[s], a1[s]);
        *(float2*)(out + ((((long long)b * SS + s) * HH) + h) * WW + w) = o;
    }
}

extern "C" void kernel_launch(void* const* d_in, const int* in_sizes, int n_in,
                              void* d_out, int out_size) {
    const float* src = (const float*)d_in[0];
    const float* tgt = (const float*)d_in[1];
    float* out = (float*)d_out;

    dim3 block(BX, BY);                    // 16 x 8 = 128 threads
    dim3 grid(WW / TW, HH / TH, BB);       // 5 x 12 x 4 = 240 CTAs
    cost_volume_kernel<<<grid, block>>>(src, tgt, out);
}

// round 2
// speedup vs baseline: 3.8912x; 3.8912x over previous
#include <cuda_runtime.h>

// Problem constants (fixed by setup_inputs)
#define BB 4
#define CC 128
#define HH 96
#define WW 160
#define RR 4
#define SS 17   // 1 + 4*R

// Tiling
#define TW 32          // tile width in pixels
#define TH 8           // tile height in pixels
#define PX 2           // pixels per thread along w
#define BX (TW / PX)   // 16
#define BY TH          // 8
#define NTHREADS (BX * BY)   // 128
#define HALO_W (TW + 2 * RR) // 40
#define HALO_H (TH + 2 * RR) // 16

#define NCHUNK 8                 // channel chunks
#define CPK (CC / NCHUNK)        // 16 channels per chunk

__global__ __launch_bounds__(NTHREADS)
void cost_volume_kernel(const float* __restrict__ src,
                        const float* __restrict__ tgt,
                        float* __restrict__ out) {
    // all CPK channel halo tiles staged once: 16 * 16 * 40 * 4B = 40KB
    __shared__ float sm[CPK][HALO_H][HALO_W];

    const int tx = threadIdx.x;
    const int ty = threadIdx.y;
    const int tid = ty * BX + tx;
    const int w0 = blockIdx.x * TW;
    const int h0 = blockIdx.y * TH;
    const int b     = blockIdx.z >> 3;   // NCHUNK = 8
    const int chunk = blockIdx.z & 7;
    const int c0 = chunk * CPK;
    const int lx = 2 * tx;
    const int w  = w0 + lx;
    const int h  = h0 + ty;

    const float* tgtb = tgt + ((long long)b * CC + c0) * HH * WW;
    const float* srcp = src + (((long long)b * CC + c0) * HH + h) * WW + w;

    // ---- cooperative staging of CPK channel halo tiles (zero-padded) ----
#pragma unroll 4
    for (int i = tid; i < CPK * HALO_H * HALO_W; i += NTHREADS) {
        int ch  = i / (HALO_H * HALO_W);
        int rem = i - ch * (HALO_H * HALO_W);
        int r   = rem / HALO_W;
        int cl  = rem - r * HALO_W;
        int gr  = h0 - RR + r;
        int gc  = w0 - RR + cl;
        float v = 0.f;
        if ((unsigned)gr < (unsigned)HH && (unsigned)gc < (unsigned)WW)
            v = tgtb[(ch * HH + gr) * WW + gc];
        sm[ch][r][cl] = v;
    }
    __syncthreads();

    // ---- compute: 17 shifts x 2 pixels, accumulate over CPK channels ----
    float a0[SS], a1[SS];
#pragma unroll
    for (int s = 0; s < SS; s++) { a0[s] = 0.f; a1[s] = 0.f; }

#pragma unroll 4
    for (int ch = 0; ch < CPK; ch++) {
        const float2 sv = *(const float2*)(srcp + (long long)ch * HH * WW);

        // horizontal row (dh = 0): cols lx .. lx+9 -> vals[0..9]
        float vals[10];
#pragma unroll
        for (int j = 0; j < 5; j++) {
            float2 t = *(const float2*)&sm[ch][ty + RR][lx + 2 * j];
            vals[2 * j]     = t.x;
            vals[2 * j + 1] = t.y;
        }
        a0[0] += sv.x * vals[4];
        a1[0] += sv.y * vals[5];
#pragma unroll
        for (int i2 = 1; i2 <= RR; i2++) {
            a0[4 * i2 - 1] += sv.x * vals[4 - i2];
            a0[4 * i2]     += sv.x * vals[4 + i2];
            a1[4 * i2 - 1] += sv.y * vals[5 - i2];
            a1[4 * i2]     += sv.y * vals[5 + i2];
        }
        // vertical: s = 4i-3 : (-i,0) ; s = 4i-2 : (+i,0)
#pragma unroll
        for (int i2 = 1; i2 <= RR; i2++) {
            float2 tu = *(const float2*)&sm[ch][ty + RR - i2][lx + RR];
            float2 td = *(const float2*)&sm[ch][ty + RR + i2][lx + RR];
            a0[4 * i2 - 3] += sv.x * tu.x;
            a1[4 * i2 - 3] += sv.y * tu.y;
            a0[4 * i2 - 2] += sv.x * td.x;
            a1[4 * i2 - 2] += sv.y * td.y;
        }
    }

    // ---- combine partial sums across channel chunks via float2 atomics ----
#pragma unroll
    for (int s = 0; s < SS; s++) {
        float2* p = (float2*)(out + ((((long long)b * SS + s) * HH) + h) * WW + w);
        atomicAdd(p, make_float2(a0[s], a1[s]));
    }
}

extern "C" void kernel_launch(void* const* d_in, const int* in_sizes, int n_in,
                              void* d_out, int out_size) {
    const float* src = (const float*)d_in[0];
    const float* tgt = (const float*)d_in[1];
    float* out = (float*)d_out;

    cudaMemsetAsync(out, 0, (size_t)out_size * sizeof(float), 0);

    dim3 block(BX, BY);                         // 16 x 8 = 128 threads
    dim3 grid(WW / TW, HH / TH, BB * NCHUNK);   // 5 x 12 x 32 = 1920 CTAs
    cost_volume_kernel<<<grid, block>>>(src, tgt, out);
}

// round 3
// speedup vs baseline: 5.1723x; 1.3292x over previous
#include <cuda_runtime.h>
#include <cstdint>

// Problem constants (fixed by setup_inputs)
#define BB 4
#define CC 128
#define HH 96
#define WW 160
#define RR 4
#define SS 17   // 1 + 4*R

// Tiling
#define TW 32
#define TH 8
#define BX 16          // threads in w (2 px each)
#define BY 8
#define NTHREADS (BX * BY)   // 128
#define HALO_W (TW + 2 * RR) // 40
#define HALO_H (TH + 2 * RR) // 16
#define HALO_N (HALO_H * HALO_W)  // 640

#define NCHUNK 8
#define CPK (CC / NCHUNK)    // 16 channels per chunk
#define HW (HH * WW)

// packed f32x2 fma: acc = a*b + acc  (elementwise on 2 floats)
__device__ __forceinline__ void ffma2(uint64_t& acc, uint64_t a, uint64_t b) {
    asm("fma.rn.f32x2 %0, %1, %2, %0;" : "+l"(acc) : "l"(a), "l"(b));
}
__device__ __forceinline__ uint64_t pack2(float lo, float hi) {
    uint64_t r;
    asm("mov.b64 %0, {%1, %2};" : "=l"(r) : "f"(lo), "f"(hi));
    return r;
}

__global__ __launch_bounds__(NTHREADS, 6)
void cost_volume_kernel(const float* __restrict__ src,
                        const float* __restrict__ tgt,
                        float* __restrict__ out) {
    __shared__ float sm[CPK * HALO_N];   // 40 KB

    const int tx = threadIdx.x;
    const int ty = threadIdx.y;
    const int tid = ty * BX + tx;
    const int w0 = blockIdx.x * TW;
    const int h0 = blockIdx.y * TH;
    const int b     = blockIdx.z >> 3;
    const int chunk = blockIdx.z & 7;
    const int c0 = chunk * CPK;
    const int lx = 2 * tx;
    const int w  = w0 + lx;
    const int h  = h0 + ty;

    const float* tgtb = tgt + ((long long)b * CC + c0) * HW;
    const float* srcp = src + (((long long)b * CC + c0) * HH + h) * WW + w;

    // ---- staging: precompute 5 offsets/masks once, then unrolled LDG/STS ----
    int soff[5], goff[5];
    bool val[5];
#pragma unroll
    for (int k = 0; k < 5; k++) {
        int pos = tid + k * NTHREADS;     // 0..639
        int r   = pos / HALO_W;
        int cl  = pos - r * HALO_W;
        int gr  = h0 - RR + r;
        int gc  = w0 - RR + cl;
        soff[k] = pos;
        val[k]  = ((unsigned)gr < (unsigned)HH) & ((unsigned)gc < (unsigned)WW);
        goff[k] = gr * WW + gc;
    }
#pragma unroll
    for (int ch = 0; ch < CPK; ch++) {
        const float* tc = tgtb + ch * HW;
        float* sc = sm + ch * HALO_N;
#pragma unroll
        for (int k = 0; k < 5; k++)
            sc[soff[k]] = val[k] ? tc[goff[k]] : 0.f;
    }
    __syncthreads();

    // ---- compute: 17 packed accumulators over 16 channels (fully unrolled) ----
    uint64_t acc[SS];
#pragma unroll
    for (int s = 0; s < SS; s++) acc[s] = 0ull;

    const int rowbase = (ty + RR) * HALO_W + lx;     // this thread's row, col lx

#pragma unroll
    for (int ch = 0; ch < CPK; ch++) {
        // src pixel pair (64-bit load)
        uint64_t sv = *(const uint64_t*)(srcp + ch * HW);

        const float* smc = sm + ch * HALO_N;
        // horizontal row: 10 values v[0..9] = cols lx..lx+9 (5 aligned LDS.64)
        float v[10];
#pragma unroll
        for (int j = 0; j < 5; j++) {
            float2 t = *(const float2*)(smc + rowbase + 2 * j);
            v[2 * j] = t.x; v[2 * j + 1] = t.y;
        }
        const uint64_t* hp = (const uint64_t*)(smc + rowbase);  // aligned pairs

        // s=0: center pair (v4,v5) = hp[2]
        ffma2(acc[0], sv, hp[2]);
        // i=1: L=(v3,v4) R=(v5,v6)  (packed from scalars)
        ffma2(acc[3], sv, pack2(v[3], v[4]));
        ffma2(acc[4], sv, pack2(v[5], v[6]));
        // i=2: L=(v2,v3)=hp[1]  R=(v6,v7)=hp[3]
        ffma2(acc[7], sv, hp[1]);
        ffma2(acc[8], sv, hp[3]);
        // i=3: L=(v1,v2) R=(v7,v8)
        ffma2(acc[11], sv, pack2(v[1], v[2]));
        ffma2(acc[12], sv, pack2(v[7], v[8]));
        // i=4: L=(v0,v1)=hp[0]  R=(v8,v9)=hp[4]
        ffma2(acc[15], sv, hp[0]);
        ffma2(acc[16], sv, hp[4]);

        // vertical: s=4i-3 (up), s=4i-2 (down): aligned pairs at col lx+RR
#pragma unroll
        for (int i2 = 1; i2 <= RR; i2++) {
            uint64_t tu = *(const uint64_t*)(smc + (ty + RR - i2) * HALO_W + lx + RR);
            uint64_t td = *(const uint64_t*)(smc + (ty + RR + i2) * HALO_W + lx + RR);
            ffma2(acc[4 * i2 - 3], sv, tu);
            ffma2(acc[4 * i2 - 2], sv, td);
        }
    }

    // ---- combine partials across chunks via float2 atomics ----
    float* ob = out + ((((long long)b * SS) * HH) + h) * WW + w;
#pragma unroll
    for (int s = 0; s < SS; s++) {
        float2 o;
        asm("mov.b64 {%0, %1}, %2;" : "=f"(o.x), "=f"(o.y) : "l"(acc[s]));
        atomicAdd((float2*)(ob + s * HW), o);
    }
}

extern "C" void kernel_launch(void* const* d_in, const int* in_sizes, int n_in,
                              void* d_out, int out_size) {
    const float* src = (const float*)d_in[0];
    const float* tgt = (const float*)d_in[1];
    float* out = (float*)d_out;

    cudaMemsetAsync(out, 0, (size_t)out_size * sizeof(float), 0);

    dim3 block(BX, BY);
    dim3 grid(WW / TW, HH / TH, BB * NCHUNK);   // 5 x 12 x 32 = 1920 CTAs
    cost_volume_kernel<<<grid, block>>>(src, tgt, out);
}